// round 12
// baseline (speedup 1.0000x reference)
#include <cuda_runtime.h>
#include <cuda_bf16.h>
#include <stdint.h>
#include <math.h>

#define B_ 8
#define T_ 4096

// smem layout (bytes)
#define OFF_CH 0          // cells hi: 66 rows x 272B
#define OFF_CL 17952      // cells lo
#define OFF_HH 35904      // H hi: 64 rows x 272B (128 bf16 cols + pad)
#define OFF_HL 53312      // H lo
#define OFF_W  70720      // W region: 2 buffers x (hi 10240 + lo 10240)
#define WBUF   20480
#define WLO    10240
#define SMEM_BYTES 111680

struct Sel { float rulew[8]; float alpha; int n_evolve; };
__device__ Sel g_sel;
__device__ float g_buf[2][B_*T_*128];          // ping-pong state
__device__ float g_outa[B_*T_*128];            // rule-sum accumulator (L2-resident)
__device__ __nv_bfloat16 g_w1h[8*256*384];     // [r][n=256][k=384] hi
__device__ __nv_bfloat16 g_w1l[8*256*384];     // lo
__device__ __nv_bfloat16 g_w2h[8*128*256];     // [r][n=128][k=256] hi
__device__ __nv_bfloat16 g_w2l[8*128*256];     // lo

__device__ __forceinline__ float gelu_exact(float x){
    return 0.5f*x*(1.0f+erff(x*0.70710678118654752f));
}
__device__ __forceinline__ uint32_t smem_u32(const void* p){
    uint32_t a;
    asm("{ .reg .u64 t; cvta.to.shared.u64 t, %1; cvt.u32.u64 %0, t; }" : "=r"(a) : "l"(p));
    return a;
}
__device__ __forceinline__ void ldsm4(uint32_t* r, uint32_t addr){
    asm volatile("ldmatrix.sync.aligned.m8n8.x4.shared.b16 {%0,%1,%2,%3}, [%4];"
        : "=r"(r[0]),"=r"(r[1]),"=r"(r[2]),"=r"(r[3]) : "r"(addr));
}
__device__ __forceinline__ void mma16816(float* c, const uint32_t* a, uint32_t b0, uint32_t b1){
    asm volatile("mma.sync.aligned.m16n8k16.row.col.f32.bf16.bf16.f32 "
        "{%0,%1,%2,%3}, {%4,%5,%6,%7}, {%8,%9}, {%0,%1,%2,%3};"
        : "+f"(c[0]),"+f"(c[1]),"+f"(c[2]),"+f"(c[3])
        : "r"(a[0]),"r"(a[1]),"r"(a[2]),"r"(a[3]), "r"(b0),"r"(b1));
}
__device__ __forceinline__ uint32_t pack_bf2(float a, float b){
    __nv_bfloat162 t; t.x = __float2bfloat16_rn(a); t.y = __float2bfloat16_rn(b);
    return *(uint32_t*)&t;
}

// ---------------------------------------------------------------------------
// Weight prep: transpose + fp32 -> bf16 hi/lo split
// ---------------------------------------------------------------------------
__global__ void prep_w1(const float* __restrict__ W1){
    int idx = blockIdx.x*256 + threadIdx.x;        // 786432
    int r = idx / 98304, rem = idx - r*98304;
    int k = rem >> 8, n = rem & 255;
    float v = W1[idx];
    __nv_bfloat16 hi = __float2bfloat16_rn(v);
    size_t o = (size_t)(r*256 + n)*384 + k;
    g_w1h[o] = hi;
    g_w1l[o] = __float2bfloat16_rn(v - __bfloat162float(hi));
}
__global__ void prep_w2(const float* __restrict__ W2){
    int idx = blockIdx.x*256 + threadIdx.x;        // 262144
    int r = idx >> 15, rem = idx & 32767;
    int h = rem >> 7, n = rem & 127;
    float v = W2[idx];
    __nv_bfloat16 hi = __float2bfloat16_rn(v);
    size_t o = (size_t)(r*128 + n)*256 + h;
    g_w2h[o] = hi;
    g_w2l[o] = __float2bfloat16_rn(v - __bfloat162float(hi));
}

// ---------------------------------------------------------------------------
// Selector
// ---------------------------------------------------------------------------
__global__ void selector_kernel(const float* __restrict__ c,
    const float* __restrict__ rW1, const float* __restrict__ rb1,
    const float* __restrict__ rW2, const float* __restrict__ rb2,
    const float* __restrict__ sW1, const float* __restrict__ sb1,
    const float* __restrict__ sW2, const float* __restrict__ sb2,
    const float* __restrict__ aW1, const float* __restrict__ ab1,
    const float* __restrict__ aW2, const float* __restrict__ ab2)
{
    __shared__ float cs[128], hidA[64], logA[8], hidB[32], logB[7], hidC[32];
    int t = threadIdx.x;
    cs[t] = c[t];
    __syncthreads();
    if (t < 64) {
        float s = rb1[t];
        for (int k = 0; k < 128; k++) s = fmaf(cs[k], rW1[k*64 + t], s);
        hidA[t] = gelu_exact(s);
    } else if (t < 96) {
        int j = t - 64; float s = sb1[j];
        for (int k = 0; k < 128; k++) s = fmaf(cs[k], sW1[k*32 + j], s);
        hidB[j] = gelu_exact(s);
    } else {
        int j = t - 96; float s = ab1[j];
        for (int k = 0; k < 128; k++) s = fmaf(cs[k], aW1[k*32 + j], s);
        hidC[j] = gelu_exact(s);
    }
    __syncthreads();
    if (t < 8) {
        float s = rb2[t];
        for (int k = 0; k < 64; k++) s = fmaf(hidA[k], rW2[k*8 + t], s);
        logA[t] = s;
    } else if (t < 15) {
        int j = t - 8; float s = sb2[j];
        for (int k = 0; k < 32; k++) s = fmaf(hidB[k], sW2[k*7 + j], s);
        logB[j] = s;
    }
    __syncthreads();
    if (t == 0) {
        float m = -1e30f;
        for (int i = 0; i < 8; i++) m = fmaxf(m, logA[i]);
        float e[8], den = 0.f;
        for (int i = 0; i < 8; i++) { e[i] = expf(logA[i] - m); den += e[i]; }
        for (int i = 0; i < 8; i++) g_sel.rulew[i] = e[i] / den;
    } else if (t == 1) {
        float m = -1e30f;
        for (int i = 0; i < 7; i++) m = fmaxf(m, logB[i]);
        float e[7], den = 0.f;
        for (int i = 0; i < 7; i++) { e[i] = expf(logB[i] - m); den += e[i]; }
        float ns = 0.f;
        for (int i = 0; i < 7; i++) ns += (e[i] / den) * (2.0f + (float)i);
        int n = (int)floorf(ns + 0.5f);
        g_sel.n_evolve = max(2, min(8, n));
    } else if (t == 2) {
        float s = ab2[0];
        for (int k = 0; k < 32; k++) s = fmaf(hidC[k], aW2[k], s);
        g_sel.alpha = 0.1f + 0.8f / (1.0f + expf(-s));
    }
}

// ---------------------------------------------------------------------------
// W chunk staging: [128 rows x 32 k] hi+lo, 80B row stride (conflict-free).
// t<128 stages hi plane, t>=128 stages lo plane; 64B per thread.
// ---------------------------------------------------------------------------
__device__ __forceinline__ void stage_chunk(char* sm, int tid,
    const __nv_bfloat16* __restrict__ hi, const __nv_bfloat16* __restrict__ lo,
    size_t base, int kstride, int buf)
{
    int plane = tid >> 7;
    int row = tid & 127;
    const __nv_bfloat16* src = (plane ? lo : hi) + base + (size_t)row*kstride;
    char* d = sm + OFF_W + buf*WBUF + plane*WLO + row*80;
    #pragma unroll
    for (int i = 0; i < 4; i++)
        *(uint4*)(d + i*16) = *(const uint4*)(src + i*8);
}

// ---------------------------------------------------------------------------
// Fused evolve step: 64-row tiles, 8 warps as 2M(m32) x 4N(n32), 2 CTAs/SM
// ---------------------------------------------------------------------------
__global__ void __launch_bounds__(256, 2) evolve_mma(
    const float* __restrict__ src_in,
    const float* __restrict__ b1, const float* __restrict__ b2, int iter)
{
    if (iter >= g_sel.n_evolve) return;
    const float* __restrict__ src = iter ? g_buf[iter & 1] : src_in;
    float* __restrict__ dst = g_buf[(iter + 1) & 1];

    extern __shared__ char sm[];
    const uint32_t sb = smem_u32(sm);
    const int tid = threadIdx.x, w = tid >> 5, lane = tid & 31;
    const int m0 = blockIdx.x*64, bidx = m0 >> 12, t0 = m0 & 4095;

    // ---- load 66-row halo'd cells tile -> bf16 hi/lo planes ----
    for (int idx = tid; idx < 66*32; idx += 256) {
        int row = idx >> 5, q = idx & 31;
        int tt = (t0 - 1 + row) & 4095;
        float4 v = __ldg((const float4*)&src[((size_t)(bidx << 12) + tt)*128 + q*4]);
        __nv_bfloat16 h0 = __float2bfloat16_rn(v.x), h1 = __float2bfloat16_rn(v.y);
        __nv_bfloat16 h2 = __float2bfloat16_rn(v.z), h3 = __float2bfloat16_rn(v.w);
        uint32_t lo01 = pack_bf2(v.x - __bfloat162float(h0), v.y - __bfloat162float(h1));
        uint32_t lo23 = pack_bf2(v.z - __bfloat162float(h2), v.w - __bfloat162float(h3));
        __nv_bfloat162 hp0; hp0.x = h0; hp0.y = h1;
        __nv_bfloat162 hp1; hp1.x = h2; hp1.y = h3;
        *(uint2*)(sm + OFF_CH + row*272 + q*8) = make_uint2(*(uint32_t*)&hp0, *(uint32_t*)&hp1);
        *(uint2*)(sm + OFF_CL + row*272 + q*8) = make_uint2(lo01, lo23);
    }

    const int mw = w & 1;             // m32 slice
    const int nw = w >> 1;            // n32 group (0..3)
    const int lrow    = lane & 15;
    const int lsel8   = (lane >> 4) << 3;
    const int rowpatB = (lane & 7) + ((lane >> 4) << 3);
    const int selB16  = ((lane >> 3) & 1) * 16;

    #pragma unroll 1
    for (int r = 0; r < 8; r++) {
        float acc2[2][4][4];
        #pragma unroll
        for (int mt = 0; mt < 2; mt++)
            #pragma unroll
            for (int fr = 0; fr < 4; fr++)
                #pragma unroll
                for (int q = 0; q < 4; q++) acc2[mt][fr][q] = 0.f;

        #pragma unroll 1
        for (int nh = 0; nh < 2; nh++) {
            // ============ GEMM1: C1[64x128] over K=384, k32 chunks ============
            float C1[2][4][4];
            #pragma unroll
            for (int mt = 0; mt < 2; mt++)
                #pragma unroll
                for (int fr = 0; fr < 4; fr++)
                    #pragma unroll
                    for (int q = 0; q < 4; q++) C1[mt][fr][q] = 0.f;

            __syncthreads();               // W region + H region free
            stage_chunk(sm, tid, g_w1h, g_w1l, (size_t)(r*256 + nh*128)*384, 384, 0);
            #pragma unroll 1
            for (int c = 0; c < 12; c++) {
                __syncthreads();
                if (c + 1 < 12)
                    stage_chunk(sm, tid, g_w1h, g_w1l,
                        (size_t)(r*256 + nh*128)*384 + ((c+1)>>2)*128 + ((c+1)&3)*32,
                        384, (c+1)&1);
                const int p = c >> 2;
                const int dp = (p == 0) ? 0 : ((p == 1) ? -1 : 1);
                const int kcol = (c & 3)*32;
                const uint32_t aB = sb + OFF_CH
                    + (uint32_t)(mw*32 + 1 + dp + lrow)*272 + (uint32_t)(kcol + lsel8)*2;
                const uint32_t wB = sb + OFF_W + (uint32_t)(c & 1)*WBUF
                    + (uint32_t)(nw*32 + rowpatB)*80 + (uint32_t)selB16;
                #pragma unroll
                for (int kk = 0; kk < 2; kk++) {
                    uint32_t ah[2][4], al[2][4];
                    #pragma unroll
                    for (int mt = 0; mt < 2; mt++) {
                        ldsm4(ah[mt], aB + mt*(16*272) + kk*32);
                        ldsm4(al[mt], aB + (OFF_CL-OFF_CH) + mt*(16*272) + kk*32);
                    }
                    #pragma unroll
                    for (int g = 0; g < 2; g++) {
                        uint32_t bh[4], bl[4];
                        ldsm4(bh, wB + g*(16*80) + kk*32);
                        ldsm4(bl, wB + WLO + g*(16*80) + kk*32);
                        #pragma unroll
                        for (int mt = 0; mt < 2; mt++) {
                            mma16816(C1[mt][2*g],   ah[mt], bh[0], bh[1]);
                            mma16816(C1[mt][2*g+1], ah[mt], bh[2], bh[3]);
                            mma16816(C1[mt][2*g],   al[mt], bh[0], bh[1]);
                            mma16816(C1[mt][2*g+1], al[mt], bh[2], bh[3]);
                            mma16816(C1[mt][2*g],   ah[mt], bl[0], bl[1]);
                            mma16816(C1[mt][2*g+1], ah[mt], bl[2], bl[3]);
                        }
                    }
                }
            }
            // ---- GELU + split -> H planes; stage W2 chunk0 (buf0 safe) ----
            #pragma unroll
            for (int mt = 0; mt < 2; mt++)
                #pragma unroll
                for (int fr = 0; fr < 4; fr++) {
                    int row = mw*32 + mt*16 + (lane >> 2);
                    int col = nw*32 + fr*8 + (lane & 3)*2;
                    float2 bb = __ldg((const float2*)&b1[r*256 + nh*128 + col]);
                    float g0 = gelu_exact(C1[mt][fr][0] + bb.x);
                    float g1 = gelu_exact(C1[mt][fr][1] + bb.y);
                    float g2 = gelu_exact(C1[mt][fr][2] + bb.x);
                    float g3 = gelu_exact(C1[mt][fr][3] + bb.y);
                    __nv_bfloat16 q0 = __float2bfloat16_rn(g0), q1 = __float2bfloat16_rn(g1);
                    __nv_bfloat16 q2 = __float2bfloat16_rn(g2), q3 = __float2bfloat16_rn(g3);
                    __nv_bfloat162 t01; t01.x = q0; t01.y = q1;
                    __nv_bfloat162 t23; t23.x = q2; t23.y = q3;
                    *(uint32_t*)(sm + OFF_HH + row*272 + col*2)     = *(uint32_t*)&t01;
                    *(uint32_t*)(sm + OFF_HH + (row+8)*272 + col*2) = *(uint32_t*)&t23;
                    *(uint32_t*)(sm + OFF_HL + row*272 + col*2)     =
                        pack_bf2(g0 - __bfloat162float(q0), g1 - __bfloat162float(q1));
                    *(uint32_t*)(sm + OFF_HL + (row+8)*272 + col*2) =
                        pack_bf2(g2 - __bfloat162float(q2), g3 - __bfloat162float(q3));
                }
            stage_chunk(sm, tid, g_w2h, g_w2l, (size_t)(r*128)*256 + nh*128, 256, 0);
            __syncthreads();               // H visible + W2 chunk0 ready
            // ============ GEMM2: acc2 += H[64x128] @ W2[128n x 128k] ============
            #pragma unroll 1
            for (int c2 = 0; c2 < 4; c2++) {
                if (c2 + 1 < 4)
                    stage_chunk(sm, tid, g_w2h, g_w2l,
                        (size_t)(r*128)*256 + nh*128 + (c2+1)*32, 256, (c2+1)&1);
                const uint32_t hB = sb + OFF_HH
                    + (uint32_t)(mw*32 + lrow)*272 + (uint32_t)(c2*32 + lsel8)*2;
                const uint32_t wB2 = sb + OFF_W + (uint32_t)(c2 & 1)*WBUF
                    + (uint32_t)(nw*32 + rowpatB)*80 + (uint32_t)selB16;
                #pragma unroll
                for (int kk = 0; kk < 2; kk++) {
                    uint32_t ah[2][4], al[2][4];
                    #pragma unroll
                    for (int mt = 0; mt < 2; mt++) {
                        ldsm4(ah[mt], hB + mt*(16*272) + kk*32);
                        ldsm4(al[mt], hB + (OFF_HL-OFF_HH) + mt*(16*272) + kk*32);
                    }
                    #pragma unroll
                    for (int g = 0; g < 2; g++) {
                        uint32_t bh[4], bl[4];
                        ldsm4(bh, wB2 + g*(16*80) + kk*32);
                        ldsm4(bl, wB2 + WLO + g*(16*80) + kk*32);
                        #pragma unroll
                        for (int mt = 0; mt < 2; mt++) {
                            mma16816(acc2[mt][2*g],   ah[mt], bh[0], bh[1]);
                            mma16816(acc2[mt][2*g+1], ah[mt], bh[2], bh[3]);
                            mma16816(acc2[mt][2*g],   al[mt], bh[0], bh[1]);
                            mma16816(acc2[mt][2*g+1], al[mt], bh[2], bh[3]);
                            mma16816(acc2[mt][2*g],   ah[mt], bl[0], bl[1]);
                            mma16816(acc2[mt][2*g+1], ah[mt], bl[2], bl[3]);
                        }
                    }
                }
                if (c2 + 1 < 4) __syncthreads();
            }
        }
        // ---- rule epilogue: g_outa (+)= rw * tanh(acc2 + b2), per-thread-owned ----
        const float rw = g_sel.rulew[r];
        #pragma unroll
        for (int mt = 0; mt < 2; mt++)
            #pragma unroll
            for (int fr = 0; fr < 4; fr++) {
                int row = m0 + mw*32 + mt*16 + (lane >> 2);
                int col = nw*32 + fr*8 + (lane & 3)*2;
                float2 bb = __ldg((const float2*)&b2[r*128 + col]);
                float v0 = rw*tanhf(acc2[mt][fr][0] + bb.x);
                float v1 = rw*tanhf(acc2[mt][fr][1] + bb.y);
                float v2 = rw*tanhf(acc2[mt][fr][2] + bb.x);
                float v3 = rw*tanhf(acc2[mt][fr][3] + bb.y);
                float* p0 = &g_outa[(size_t)row*128 + col];
                float* p1 = &g_outa[(size_t)(row+8)*128 + col];
                if (r == 0) {
                    *(float2*)p0 = make_float2(v0, v1);
                    *(float2*)p1 = make_float2(v2, v3);
                } else {
                    float2 a0 = *(float2*)p0, a1 = *(float2*)p1;
                    *(float2*)p0 = make_float2(a0.x + v0, a0.y + v1);
                    *(float2*)p1 = make_float2(a1.x + v2, a1.y + v3);
                }
            }
    }

    // ---- final blend + coalesced store ----
    __syncthreads();   // intra-CTA g_outa visibility
    const float alpha = g_sel.alpha, beta = 1.0f - alpha;
    for (int i = tid; i < 64*64; i += 256) {
        int row = i >> 6, c2p = (i & 63)*2;
        size_t go = (size_t)(m0 + row)*128 + c2p;
        float2 ov = *(float2*)&g_outa[go];
        float2 sv = __ldg((const float2*)&src[go]);
        float2 o;
        o.x = alpha*sv.x + beta*ov.x;
        o.y = alpha*sv.y + beta*ov.y;
        *(float2*)&dst[go] = o;
    }
}

// ---------------------------------------------------------------------------
// Final LayerNorm
// ---------------------------------------------------------------------------
__global__ void ln_kernel(const float* __restrict__ g, const float* __restrict__ bt,
                          float* __restrict__ out)
{
    const int warp = threadIdx.x >> 5, lane = threadIdx.x & 31;
    const int row  = blockIdx.x * 8 + warp;
    const float* __restrict__ src = g_buf[g_sel.n_evolve & 1];
    float4 v = *(const float4*)&src[(size_t)row*128 + lane*4];
    float s  = v.x + v.y + v.z + v.w;
    float sq = v.x*v.x + v.y*v.y + v.z*v.z + v.w*v.w;
    #pragma unroll
    for (int o = 16; o; o >>= 1) {
        s  += __shfl_xor_sync(0xffffffffu, s,  o);
        sq += __shfl_xor_sync(0xffffffffu, sq, o);
    }
    float mu  = s * (1.0f/128.0f);
    float var = sq * (1.0f/128.0f) - mu*mu;
    float rs  = rsqrtf(var + 1e-5f);
    float4 gv = *(const float4*)&g[lane*4];
    float4 bv = *(const float4*)&bt[lane*4];
    float4 o4;
    o4.x = (v.x - mu)*rs*gv.x + bv.x;
    o4.y = (v.y - mu)*rs*gv.y + bv.y;
    o4.z = (v.z - mu)*rs*gv.z + bv.z;
    o4.w = (v.w - mu)*rs*gv.w + bv.w;
    *(float4*)&out[(size_t)row*128 + lane*4] = o4;
}

// ---------------------------------------------------------------------------
extern "C" void kernel_launch(void* const* d_in, const int* in_sizes, int n_in,
                              void* d_out, int out_size)
{
    const float* cells = (const float*)d_in[0];
    const float* c_st  = (const float*)d_in[1];
    const float* W1    = (const float*)d_in[2];
    const float* b1    = (const float*)d_in[3];
    const float* W2    = (const float*)d_in[4];
    const float* b2    = (const float*)d_in[5];
    const float* rW1   = (const float*)d_in[6];
    const float* rb1   = (const float*)d_in[7];
    const float* rW2   = (const float*)d_in[8];
    const float* rb2   = (const float*)d_in[9];
    const float* sW1   = (const float*)d_in[10];
    const float* sb1   = (const float*)d_in[11];
    const float* sW2   = (const float*)d_in[12];
    const float* sb2   = (const float*)d_in[13];
    const float* aW1   = (const float*)d_in[14];
    const float* ab1   = (const float*)d_in[15];
    const float* aW2   = (const float*)d_in[16];
    const float* ab2   = (const float*)d_in[17];
    const float* lng   = (const float*)d_in[18];
    const float* lnb   = (const float*)d_in[19];
    float* out = (float*)d_out;

    cudaFuncSetAttribute(evolve_mma, cudaFuncAttributeMaxDynamicSharedMemorySize, SMEM_BYTES);

    prep_w1<<<3072, 256>>>(W1);
    prep_w2<<<1024, 256>>>(W2);
    selector_kernel<<<1, 128>>>(c_st, rW1, rb1, rW2, rb2,
                                sW1, sb1, sW2, sb2, aW1, ab1, aW2, ab2);
    for (int i = 0; i < 8; i++)
        evolve_mma<<<512, 256, SMEM_BYTES>>>(cells, b1, b2, i);
    ln_kernel<<<B_*T_/8, 256>>>(lng, lnb, out);
}

// round 14
// speedup vs baseline: 1.8442x; 1.8442x over previous
#include <cuda_runtime.h>
#include <cuda_bf16.h>
#include <stdint.h>
#include <math.h>

#define B_ 8
#define T_ 4096

// smem layout (bytes) — 128-row tile, 512-thread CTA
#define OFF_CH 0          // cells hi: 130 rows x 272B
#define OFF_CL 35360      // cells lo
#define OFF_HH 70720      // H hi: 128 x 144B
#define OFF_HL 89152      // H lo
#define OFF_W  107584     // shared W region: W1 2 bufs x 18432 | W2 hi+lo 36864
#define W1BUF  18432
#define W1LO   9216
#define W2LO   18432
#define SMEM_BYTES 144448

struct Sel { float rulew[8]; float alpha; int n_evolve; };
__device__ Sel g_sel;
__device__ float g_buf[2][B_*T_*128];          // ping-pong state
__device__ __nv_bfloat16 g_w1h[8*256*384];     // [r][n=256][k=384] hi
__device__ __nv_bfloat16 g_w1l[8*256*384];     // lo
__device__ __nv_bfloat16 g_w2h[8*128*256];     // [r][n=128][k=256] hi
__device__ __nv_bfloat16 g_w2l[8*128*256];     // lo

__device__ __forceinline__ float gelu_exact(float x){
    return 0.5f*x*(1.0f+erff(x*0.70710678118654752f));
}
__device__ __forceinline__ uint32_t smem_u32(const void* p){
    uint32_t a;
    asm("{ .reg .u64 t; cvta.to.shared.u64 t, %1; cvt.u32.u64 %0, t; }" : "=r"(a) : "l"(p));
    return a;
}
__device__ __forceinline__ void ldsm4(uint32_t* r, uint32_t addr){
    asm volatile("ldmatrix.sync.aligned.m8n8.x4.shared.b16 {%0,%1,%2,%3}, [%4];"
        : "=r"(r[0]),"=r"(r[1]),"=r"(r[2]),"=r"(r[3]) : "r"(addr));
}
__device__ __forceinline__ void mma16816(float* c, const uint32_t* a, uint32_t b0, uint32_t b1){
    asm volatile("mma.sync.aligned.m16n8k16.row.col.f32.bf16.bf16.f32 "
        "{%0,%1,%2,%3}, {%4,%5,%6,%7}, {%8,%9}, {%0,%1,%2,%3};"
        : "+f"(c[0]),"+f"(c[1]),"+f"(c[2]),"+f"(c[3])
        : "r"(a[0]),"r"(a[1]),"r"(a[2]),"r"(a[3]), "r"(b0),"r"(b1));
}
__device__ __forceinline__ uint32_t pack_bf2(float a, float b){
    __nv_bfloat162 t; t.x = __float2bfloat16_rn(a); t.y = __float2bfloat16_rn(b);
    return *(uint32_t*)&t;
}

// ---------------------------------------------------------------------------
// Weight prep: transpose + fp32 -> bf16 hi/lo split
// ---------------------------------------------------------------------------
__global__ void prep_w1(const float* __restrict__ W1){
    int idx = blockIdx.x*256 + threadIdx.x;        // 786432
    int r = idx / 98304, rem = idx - r*98304;
    int k = rem >> 8, n = rem & 255;
    float v = W1[idx];
    __nv_bfloat16 hi = __float2bfloat16_rn(v);
    size_t o = (size_t)(r*256 + n)*384 + k;
    g_w1h[o] = hi;
    g_w1l[o] = __float2bfloat16_rn(v - __bfloat162float(hi));
}
__global__ void prep_w2(const float* __restrict__ W2){
    int idx = blockIdx.x*256 + threadIdx.x;        // 262144
    int r = idx >> 15, rem = idx & 32767;
    int h = rem >> 7, n = rem & 127;
    float v = W2[idx];
    __nv_bfloat16 hi = __float2bfloat16_rn(v);
    size_t o = (size_t)(r*128 + n)*256 + h;
    g_w2h[o] = hi;
    g_w2l[o] = __float2bfloat16_rn(v - __bfloat162float(hi));
}

// ---------------------------------------------------------------------------
// Selector
// ---------------------------------------------------------------------------
__global__ void selector_kernel(const float* __restrict__ c,
    const float* __restrict__ rW1, const float* __restrict__ rb1,
    const float* __restrict__ rW2, const float* __restrict__ rb2,
    const float* __restrict__ sW1, const float* __restrict__ sb1,
    const float* __restrict__ sW2, const float* __restrict__ sb2,
    const float* __restrict__ aW1, const float* __restrict__ ab1,
    const float* __restrict__ aW2, const float* __restrict__ ab2)
{
    __shared__ float cs[128], hidA[64], logA[8], hidB[32], logB[7], hidC[32];
    int t = threadIdx.x;
    cs[t] = c[t];
    __syncthreads();
    if (t < 64) {
        float s = rb1[t];
        for (int k = 0; k < 128; k++) s = fmaf(cs[k], rW1[k*64 + t], s);
        hidA[t] = gelu_exact(s);
    } else if (t < 96) {
        int j = t - 64; float s = sb1[j];
        for (int k = 0; k < 128; k++) s = fmaf(cs[k], sW1[k*32 + j], s);
        hidB[j] = gelu_exact(s);
    } else {
        int j = t - 96; float s = ab1[j];
        for (int k = 0; k < 128; k++) s = fmaf(cs[k], aW1[k*32 + j], s);
        hidC[j] = gelu_exact(s);
    }
    __syncthreads();
    if (t < 8) {
        float s = rb2[t];
        for (int k = 0; k < 64; k++) s = fmaf(hidA[k], rW2[k*8 + t], s);
        logA[t] = s;
    } else if (t < 15) {
        int j = t - 8; float s = sb2[j];
        for (int k = 0; k < 32; k++) s = fmaf(hidB[k], sW2[k*7 + j], s);
        logB[j] = s;
    }
    __syncthreads();
    if (t == 0) {
        float m = -1e30f;
        for (int i = 0; i < 8; i++) m = fmaxf(m, logA[i]);
        float e[8], den = 0.f;
        for (int i = 0; i < 8; i++) { e[i] = expf(logA[i] - m); den += e[i]; }
        for (int i = 0; i < 8; i++) g_sel.rulew[i] = e[i] / den;
    } else if (t == 1) {
        float m = -1e30f;
        for (int i = 0; i < 7; i++) m = fmaxf(m, logB[i]);
        float e[7], den = 0.f;
        for (int i = 0; i < 7; i++) { e[i] = expf(logB[i] - m); den += e[i]; }
        float ns = 0.f;
        for (int i = 0; i < 7; i++) ns += (e[i] / den) * (2.0f + (float)i);
        int n = (int)floorf(ns + 0.5f);
        g_sel.n_evolve = max(2, min(8, n));
    } else if (t == 2) {
        float s = ab2[0];
        for (int k = 0; k < 32; k++) s = fmaf(hidC[k], aW2[k], s);
        g_sel.alpha = 0.1f + 0.8f / (1.0f + expf(-s));
    }
}

// ---------------------------------------------------------------------------
// Staging helpers (512 threads)
// ---------------------------------------------------------------------------
// W1 chunk c: [64 n-rows x 64 k], hi+lo, stride 144B. Each thread: 1 uint4/plane.
__device__ __forceinline__ void stage_w1(char* sm, int tid, int r, int nh, int kc,
                                         int c, int buf){
    int row = tid >> 3, seg = tid & 7;
    int p = c >> 1, kcol = (c & 1)*64;
    size_t so = (size_t)(r*256 + nh*128 + kc*64 + row)*384 + p*128 + kcol + seg*8;
    char* d = sm + OFF_W + buf*W1BUF + row*144 + seg*16;
    *(uint4*)d          = *(const uint4*)(g_w1h + so);
    *(uint4*)(d + W1LO) = *(const uint4*)(g_w1l + so);
}
// W2 chunk: [128 n-rows x 64 k], hi+lo, stride 144B. Each thread: 2 uint4/plane.
__device__ __forceinline__ void stage_w2(char* sm, int tid, int r, int nh, int kc){
    int row = tid >> 2, q = tid & 3;
    size_t so = (size_t)(r*128 + row)*256 + nh*128 + kc*64 + q*16;
    char* d = sm + OFF_W + row*144 + q*32;
    *(uint4*)d               = *(const uint4*)(g_w2h + so);
    *(uint4*)(d + 16)        = *(const uint4*)(g_w2h + so + 8);
    *(uint4*)(d + W2LO)      = *(const uint4*)(g_w2l + so);
    *(uint4*)(d + W2LO + 16) = *(const uint4*)(g_w2l + so + 8);
}

// ---------------------------------------------------------------------------
// Fused evolve step: 128-row tiles, 512 threads (16 warps = 8M x 2N), 1 CTA/SM
// ---------------------------------------------------------------------------
__global__ void __launch_bounds__(512, 1) evolve_mma(
    const float* __restrict__ src_in,
    const float* __restrict__ b1, const float* __restrict__ b2, int iter)
{
    if (iter >= g_sel.n_evolve) return;
    const float* __restrict__ src = iter ? g_buf[iter & 1] : src_in;
    float* __restrict__ dst = g_buf[(iter + 1) & 1];

    extern __shared__ char sm[];
    const uint32_t sb = smem_u32(sm);
    const int tid = threadIdx.x, w = tid >> 5, lane = tid & 31;
    const int m0 = blockIdx.x*128, bidx = m0 >> 12, t0 = m0 & 4095;

    // ---- load 130-row halo'd cells tile -> bf16 hi/lo planes ----
    for (int idx = tid; idx < 130*32; idx += 512) {
        int row = idx >> 5, q = idx & 31;
        int tt = (t0 - 1 + row) & 4095;
        float4 v = __ldg((const float4*)&src[((size_t)(bidx << 12) + tt)*128 + q*4]);
        __nv_bfloat16 h0 = __float2bfloat16_rn(v.x), h1 = __float2bfloat16_rn(v.y);
        __nv_bfloat16 h2 = __float2bfloat16_rn(v.z), h3 = __float2bfloat16_rn(v.w);
        uint32_t lo01 = pack_bf2(v.x - __bfloat162float(h0), v.y - __bfloat162float(h1));
        uint32_t lo23 = pack_bf2(v.z - __bfloat162float(h2), v.w - __bfloat162float(h3));
        __nv_bfloat162 hp0; hp0.x = h0; hp0.y = h1;
        __nv_bfloat162 hp1; hp1.x = h2; hp1.y = h3;
        *(uint2*)(sm + OFF_CH + row*272 + q*8) = make_uint2(*(uint32_t*)&hp0, *(uint32_t*)&hp1);
        *(uint2*)(sm + OFF_CL + row*272 + q*8) = make_uint2(lo01, lo23);
    }

    const int mw  = w & 7;            // 16-row M slice (0..7)
    const int nw  = w >> 3;           // N half
    const int nb1 = nw*32;            // GEMM1 cols (of 64)
    const int nb2 = nw*64;            // GEMM2 cols (of 128)
    const int lrow  = lane & 15;
    const int lsel8 = (lane >> 4) << 3;
    const int nrB   = (lane & 7) + ((lane >> 4) << 3);
    const int selB16 = ((lane >> 3) & 1) * 16;

    float acc2[8][4];
    float outa[8][4];
    #pragma unroll
    for (int j = 0; j < 8; j++)
        #pragma unroll
        for (int q = 0; q < 4; q++) outa[j][q] = 0.f;

    #pragma unroll 1
    for (int r = 0; r < 8; r++) {
        #pragma unroll
        for (int j = 0; j < 8; j++)
            #pragma unroll
            for (int q = 0; q < 4; q++) acc2[j][q] = 0.f;

        #pragma unroll 1
        for (int nh = 0; nh < 2; nh++) {
            #pragma unroll 1
            for (int kc = 0; kc < 2; kc++) {
                // ============ GEMM1: C1[128x64] over K=384, k64 chunks ============
                float C1[4][4];
                #pragma unroll
                for (int j = 0; j < 4; j++)
                    #pragma unroll
                    for (int q = 0; q < 4; q++) C1[j][q] = 0.f;

                __syncthreads();                  // W region free
                stage_w1(sm, tid, r, nh, kc, 0, 0);
                #pragma unroll 1
                for (int c = 0; c < 6; c++) {
                    __syncthreads();
                    if (c + 1 < 6) stage_w1(sm, tid, r, nh, kc, c + 1, (c + 1) & 1);
                    const int p = c >> 1, kcol = (c & 1)*64;
                    const int dp = (p == 0) ? 0 : ((p == 1) ? -1 : 1);
                    const uint32_t aH = sb + OFF_CH
                        + (uint32_t)(mw*16 + 1 + dp + lrow)*272 + (uint32_t)(kcol + lsel8)*2;
                    const uint32_t aL = aH + (OFF_CL - OFF_CH);
                    const uint32_t wb = sb + OFF_W + (uint32_t)(c & 1)*W1BUF
                        + (uint32_t)(nb1 + nrB)*144 + (uint32_t)selB16;
                    #pragma unroll
                    for (int kk = 0; kk < 4; kk++) {
                        uint32_t ah[4], al[4];
                        ldsm4(ah, aH + kk*32);
                        ldsm4(al, aL + kk*32);
                        #pragma unroll
                        for (int g = 0; g < 2; g++) {
                            uint32_t bh[4], bl[4];
                            ldsm4(bh, wb + (uint32_t)g*(16*144) + kk*32);
                            ldsm4(bl, wb + W1LO + (uint32_t)g*(16*144) + kk*32);
                            mma16816(C1[g*2+0], ah, bh[0], bh[1]);
                            mma16816(C1[g*2+1], ah, bh[2], bh[3]);
                            mma16816(C1[g*2+0], al, bh[0], bh[1]);
                            mma16816(C1[g*2+1], al, bh[2], bh[3]);
                            mma16816(C1[g*2+0], ah, bl[0], bl[1]);
                            mma16816(C1[g*2+1], ah, bl[2], bl[3]);
                        }
                    }
                }
                __syncthreads();                  // all warps done with W region
                // ---- GELU + split -> H planes; stage W2 ----
                #pragma unroll
                for (int nt = 0; nt < 4; nt++) {
                    int row = mw*16 + (lane >> 2);
                    int colh = nb1 + nt*8 + (lane & 3)*2;
                    float2 bb = *(const float2*)&b1[r*256 + nh*128 + kc*64 + colh];
                    float g0 = gelu_exact(C1[nt][0] + bb.x);
                    float g1 = gelu_exact(C1[nt][1] + bb.y);
                    float g2 = gelu_exact(C1[nt][2] + bb.x);
                    float g3 = gelu_exact(C1[nt][3] + bb.y);
                    __nv_bfloat16 q0 = __float2bfloat16_rn(g0), q1 = __float2bfloat16_rn(g1);
                    __nv_bfloat16 q2 = __float2bfloat16_rn(g2), q3 = __float2bfloat16_rn(g3);
                    __nv_bfloat162 t01; t01.x = q0; t01.y = q1;
                    __nv_bfloat162 t23; t23.x = q2; t23.y = q3;
                    *(uint32_t*)(sm + OFF_HH + row*144 + colh*2)     = *(uint32_t*)&t01;
                    *(uint32_t*)(sm + OFF_HH + (row+8)*144 + colh*2) = *(uint32_t*)&t23;
                    *(uint32_t*)(sm + OFF_HL + row*144 + colh*2)     =
                        pack_bf2(g0 - __bfloat162float(q0), g1 - __bfloat162float(q1));
                    *(uint32_t*)(sm + OFF_HL + (row+8)*144 + colh*2) =
                        pack_bf2(g2 - __bfloat162float(q2), g3 - __bfloat162float(q3));
                }
                stage_w2(sm, tid, r, nh, kc);
                __syncthreads();
                // ============ GEMM2: acc2 += H[128x64] @ W2[64x128] ============
                const uint32_t hH = sb + OFF_HH + (uint32_t)(mw*16 + lrow)*144 + (uint32_t)lsel8*2;
                const uint32_t hL = hH + (OFF_HL - OFF_HH);
                const uint32_t wb2 = sb + OFF_W + (uint32_t)(nb2 + nrB)*144 + (uint32_t)selB16;
                #pragma unroll
                for (int kk = 0; kk < 4; kk++) {
                    uint32_t ah[4], al[4];
                    ldsm4(ah, hH + kk*32);
                    ldsm4(al, hL + kk*32);
                    #pragma unroll
                    for (int g = 0; g < 4; g++) {
                        uint32_t bh[4], bl[4];
                        ldsm4(bh, wb2 + (uint32_t)g*(16*144) + kk*32);
                        ldsm4(bl, wb2 + W2LO + (uint32_t)g*(16*144) + kk*32);
                        mma16816(acc2[g*2+0], ah, bh[0], bh[1]);
                        mma16816(acc2[g*2+1], ah, bh[2], bh[3]);
                        mma16816(acc2[g*2+0], al, bh[0], bh[1]);
                        mma16816(acc2[g*2+1], al, bh[2], bh[3]);
                        mma16816(acc2[g*2+0], ah, bl[0], bl[1]);
                        mma16816(acc2[g*2+1], ah, bl[2], bl[3]);
                    }
                }
            }
        }
        // ---- rule epilogue: outa += rw * tanh(acc2 + b2) ----
        const float rw = g_sel.rulew[r];
        #pragma unroll
        for (int nt = 0; nt < 8; nt++) {
            int col = nb2 + nt*8 + (lane & 3)*2;
            float2 bb = *(const float2*)&b2[r*128 + col];
            outa[nt][0] = fmaf(rw, tanhf(acc2[nt][0] + bb.x), outa[nt][0]);
            outa[nt][1] = fmaf(rw, tanhf(acc2[nt][1] + bb.y), outa[nt][1]);
            outa[nt][2] = fmaf(rw, tanhf(acc2[nt][2] + bb.x), outa[nt][2]);
            outa[nt][3] = fmaf(rw, tanhf(acc2[nt][3] + bb.y), outa[nt][3]);
        }
    }

    // ---- final blend + store ----
    const float alpha = g_sel.alpha, beta = 1.0f - alpha;
    #pragma unroll
    for (int nt = 0; nt < 8; nt++) {
        int row = m0 + mw*16 + (lane >> 2);
        int col = nb2 + nt*8 + (lane & 3)*2;
        float2 s0 = *(const float2*)&src[(size_t)row*128 + col];
        float2 s1 = *(const float2*)&src[(size_t)(row+8)*128 + col];
        float2 o0, o1;
        o0.x = alpha*s0.x + beta*outa[nt][0];
        o0.y = alpha*s0.y + beta*outa[nt][1];
        o1.x = alpha*s1.x + beta*outa[nt][2];
        o1.y = alpha*s1.y + beta*outa[nt][3];
        *(float2*)&dst[(size_t)row*128 + col]     = o0;
        *(float2*)&dst[(size_t)(row+8)*128 + col] = o1;
    }
}

// ---------------------------------------------------------------------------
// Final LayerNorm
// ---------------------------------------------------------------------------
__global__ void ln_kernel(const float* __restrict__ g, const float* __restrict__ bt,
                          float* __restrict__ out)
{
    const int warp = threadIdx.x >> 5, lane = threadIdx.x & 31;
    const int row  = blockIdx.x * 8 + warp;
    const float* __restrict__ src = g_buf[g_sel.n_evolve & 1];
    float4 v = *(const float4*)&src[(size_t)row*128 + lane*4];
    float s  = v.x + v.y + v.z + v.w;
    float sq = v.x*v.x + v.y*v.y + v.z*v.z + v.w*v.w;
    #pragma unroll
    for (int o = 16; o; o >>= 1) {
        s  += __shfl_xor_sync(0xffffffffu, s,  o);
        sq += __shfl_xor_sync(0xffffffffu, sq, o);
    }
    float mu  = s * (1.0f/128.0f);
    float var = sq * (1.0f/128.0f) - mu*mu;
    float rs  = rsqrtf(var + 1e-5f);
    float4 gv = *(const float4*)&g[lane*4];
    float4 bv = *(const float4*)&bt[lane*4];
    float4 o4;
    o4.x = (v.x - mu)*rs*gv.x + bv.x;
    o4.y = (v.y - mu)*rs*gv.y + bv.y;
    o4.z = (v.z - mu)*rs*gv.z + bv.z;
    o4.w = (v.w - mu)*rs*gv.w + bv.w;
    *(float4*)&out[(size_t)row*128 + lane*4] = o4;
}

// ---------------------------------------------------------------------------
extern "C" void kernel_launch(void* const* d_in, const int* in_sizes, int n_in,
                              void* d_out, int out_size)
{
    const float* cells = (const float*)d_in[0];
    const float* c_st  = (const float*)d_in[1];
    const float* W1    = (const float*)d_in[2];
    const float* b1    = (const float*)d_in[3];
    const float* W2    = (const float*)d_in[4];
    const float* b2    = (const float*)d_in[5];
    const float* rW1   = (const float*)d_in[6];
    const float* rb1   = (const float*)d_in[7];
    const float* rW2   = (const float*)d_in[8];
    const float* rb2   = (const float*)d_in[9];
    const float* sW1   = (const float*)d_in[10];
    const float* sb1   = (const float*)d_in[11];
    const float* sW2   = (const float*)d_in[12];
    const float* sb2   = (const float*)d_in[13];
    const float* aW1   = (const float*)d_in[14];
    const float* ab1   = (const float*)d_in[15];
    const float* aW2   = (const float*)d_in[16];
    const float* ab2   = (const float*)d_in[17];
    const float* lng   = (const float*)d_in[18];
    const float* lnb   = (const float*)d_in[19];
    float* out = (float*)d_out;

    cudaFuncSetAttribute(evolve_mma, cudaFuncAttributeMaxDynamicSharedMemorySize, SMEM_BYTES);

    prep_w1<<<3072, 256>>>(W1);
    prep_w2<<<1024, 256>>>(W2);
    selector_kernel<<<1, 128>>>(c_st, rW1, rb1, rW2, rb2,
                                sW1, sb1, sW2, sb2, aW1, ab1, aW2, ab2);
    for (int i = 0; i < 8; i++)
        evolve_mma<<<256, 512, SMEM_BYTES>>>(cells, b1, b2, i);
    ln_kernel<<<B_*T_/8, 256>>>(lng, lnb, out);
}

// round 15
// speedup vs baseline: 1.9178x; 1.0399x over previous
#include <cuda_runtime.h>
#include <cuda_bf16.h>
#include <stdint.h>
#include <math.h>

#define B_ 8
#define T_ 4096

// smem layout (bytes) — 128-row tile, 512-thread CTA
#define OFF_CH 0          // cells hi: 130 rows x 272B
#define OFF_CL 35360      // cells lo
#define OFF_HH 70720      // H hi: 128 x 144B
#define OFF_HL 89152      // H lo
#define OFF_W  107584     // shared W region: W1 2 bufs x 18432 | W2 hi+lo 36864
#define W1BUF  18432
#define W1LO   9216
#define W2LO   18432
#define SMEM_BYTES 144448

struct Sel { float rulew[8]; float alpha; int n_evolve; };
__device__ Sel g_sel;
__device__ float g_buf[2][B_*T_*128];          // ping-pong state
__device__ __nv_bfloat16 g_w1h[8*256*384];     // [r][n=256][k=384] hi
__device__ __nv_bfloat16 g_w1l[8*256*384];     // lo
__device__ __nv_bfloat16 g_w2h[8*128*256];     // [r][n=128][k=256] hi
__device__ __nv_bfloat16 g_w2l[8*128*256];     // lo

__device__ __forceinline__ float gelu_exact(float x){
    return 0.5f*x*(1.0f+erff(x*0.70710678118654752f));
}
__device__ __forceinline__ uint32_t smem_u32(const void* p){
    uint32_t a;
    asm("{ .reg .u64 t; cvta.to.shared.u64 t, %1; cvt.u32.u64 %0, t; }" : "=r"(a) : "l"(p));
    return a;
}
__device__ __forceinline__ void ldsm4(uint32_t* r, uint32_t addr){
    asm volatile("ldmatrix.sync.aligned.m8n8.x4.shared.b16 {%0,%1,%2,%3}, [%4];"
        : "=r"(r[0]),"=r"(r[1]),"=r"(r[2]),"=r"(r[3]) : "r"(addr));
}
__device__ __forceinline__ void mma16816(float* c, const uint32_t* a, uint32_t b0, uint32_t b1){
    asm volatile("mma.sync.aligned.m16n8k16.row.col.f32.bf16.bf16.f32 "
        "{%0,%1,%2,%3}, {%4,%5,%6,%7}, {%8,%9}, {%0,%1,%2,%3};"
        : "+f"(c[0]),"+f"(c[1]),"+f"(c[2]),"+f"(c[3])
        : "r"(a[0]),"r"(a[1]),"r"(a[2]),"r"(a[3]), "r"(b0),"r"(b1));
}
__device__ __forceinline__ uint32_t pack_bf2(float a, float b){
    __nv_bfloat162 t; t.x = __float2bfloat16_rn(a); t.y = __float2bfloat16_rn(b);
    return *(uint32_t*)&t;
}
__device__ __forceinline__ void cp16(uint32_t daddr, const void* gptr){
    asm volatile("cp.async.cg.shared.global [%0], [%1], 16;" :: "r"(daddr), "l"(gptr) : "memory");
}
#define CP_COMMIT() asm volatile("cp.async.commit_group;" ::: "memory")
#define CP_WAIT0()  asm volatile("cp.async.wait_group 0;" ::: "memory")

// ---------------------------------------------------------------------------
// Weight prep: transpose + fp32 -> bf16 hi/lo split
// ---------------------------------------------------------------------------
__global__ void prep_w1(const float* __restrict__ W1){
    int idx = blockIdx.x*256 + threadIdx.x;        // 786432
    int r = idx / 98304, rem = idx - r*98304;
    int k = rem >> 8, n = rem & 255;
    float v = W1[idx];
    __nv_bfloat16 hi = __float2bfloat16_rn(v);
    size_t o = (size_t)(r*256 + n)*384 + k;
    g_w1h[o] = hi;
    g_w1l[o] = __float2bfloat16_rn(v - __bfloat162float(hi));
}
__global__ void prep_w2(const float* __restrict__ W2){
    int idx = blockIdx.x*256 + threadIdx.x;        // 262144
    int r = idx >> 15, rem = idx & 32767;
    int h = rem >> 7, n = rem & 127;
    float v = W2[idx];
    __nv_bfloat16 hi = __float2bfloat16_rn(v);
    size_t o = (size_t)(r*128 + n)*256 + h;
    g_w2h[o] = hi;
    g_w2l[o] = __float2bfloat16_rn(v - __bfloat162float(hi));
}

// ---------------------------------------------------------------------------
// Selector
// ---------------------------------------------------------------------------
__global__ void selector_kernel(const float* __restrict__ c,
    const float* __restrict__ rW1, const float* __restrict__ rb1,
    const float* __restrict__ rW2, const float* __restrict__ rb2,
    const float* __restrict__ sW1, const float* __restrict__ sb1,
    const float* __restrict__ sW2, const float* __restrict__ sb2,
    const float* __restrict__ aW1, const float* __restrict__ ab1,
    const float* __restrict__ aW2, const float* __restrict__ ab2)
{
    __shared__ float cs[128], hidA[64], logA[8], hidB[32], logB[7], hidC[32];
    int t = threadIdx.x;
    cs[t] = c[t];
    __syncthreads();
    if (t < 64) {
        float s = rb1[t];
        for (int k = 0; k < 128; k++) s = fmaf(cs[k], rW1[k*64 + t], s);
        hidA[t] = gelu_exact(s);
    } else if (t < 96) {
        int j = t - 64; float s = sb1[j];
        for (int k = 0; k < 128; k++) s = fmaf(cs[k], sW1[k*32 + j], s);
        hidB[j] = gelu_exact(s);
    } else {
        int j = t - 96; float s = ab1[j];
        for (int k = 0; k < 128; k++) s = fmaf(cs[k], aW1[k*32 + j], s);
        hidC[j] = gelu_exact(s);
    }
    __syncthreads();
    if (t < 8) {
        float s = rb2[t];
        for (int k = 0; k < 64; k++) s = fmaf(hidA[k], rW2[k*8 + t], s);
        logA[t] = s;
    } else if (t < 15) {
        int j = t - 8; float s = sb2[j];
        for (int k = 0; k < 32; k++) s = fmaf(hidB[k], sW2[k*7 + j], s);
        logB[j] = s;
    }
    __syncthreads();
    if (t == 0) {
        float m = -1e30f;
        for (int i = 0; i < 8; i++) m = fmaxf(m, logA[i]);
        float e[8], den = 0.f;
        for (int i = 0; i < 8; i++) { e[i] = expf(logA[i] - m); den += e[i]; }
        for (int i = 0; i < 8; i++) g_sel.rulew[i] = e[i] / den;
    } else if (t == 1) {
        float m = -1e30f;
        for (int i = 0; i < 7; i++) m = fmaxf(m, logB[i]);
        float e[7], den = 0.f;
        for (int i = 0; i < 7; i++) { e[i] = expf(logB[i] - m); den += e[i]; }
        float ns = 0.f;
        for (int i = 0; i < 7; i++) ns += (e[i] / den) * (2.0f + (float)i);
        int n = (int)floorf(ns + 0.5f);
        g_sel.n_evolve = max(2, min(8, n));
    } else if (t == 2) {
        float s = ab2[0];
        for (int k = 0; k < 32; k++) s = fmaf(hidC[k], aW2[k], s);
        g_sel.alpha = 0.1f + 0.8f / (1.0f + expf(-s));
    }
}

// ---------------------------------------------------------------------------
// Async staging helpers (512 threads)
// ---------------------------------------------------------------------------
// W1 chunk c: [64 n-rows x 64 k], hi+lo, stride 144B. Each thread: 2 x cp16.
__device__ __forceinline__ void stage_w1_async(uint32_t sb, int tid, int r, int nh,
                                               int kc, int c, int buf){
    int row = tid >> 3, seg = tid & 7;
    int p = c >> 1, kcol = (c & 1)*64;
    size_t so = (size_t)(r*256 + nh*128 + kc*64 + row)*384 + p*128 + kcol + seg*8;
    uint32_t d = sb + OFF_W + (uint32_t)buf*W1BUF + (uint32_t)row*144 + (uint32_t)seg*16;
    cp16(d,        g_w1h + so);
    cp16(d + W1LO, g_w1l + so);
}
// W2 chunk: [128 n-rows x 64 k], hi+lo, stride 144B. Each thread: 4 x cp16.
__device__ __forceinline__ void stage_w2_async(uint32_t sb, int tid, int r, int nh,
                                               int kc){
    int row = tid >> 2, q = tid & 3;
    size_t so = (size_t)(r*128 + row)*256 + nh*128 + kc*64 + q*16;
    uint32_t d = sb + OFF_W + (uint32_t)row*144 + (uint32_t)q*32;
    cp16(d,             g_w2h + so);
    cp16(d + 16,        g_w2h + so + 8);
    cp16(d + W2LO,      g_w2l + so);
    cp16(d + W2LO + 16, g_w2l + so + 8);
}

// ---------------------------------------------------------------------------
// Fused evolve step: 128-row tiles, 512 threads (16 warps = 8M x 2N), 1 CTA/SM
// ---------------------------------------------------------------------------
__global__ void __launch_bounds__(512, 1) evolve_mma(
    const float* __restrict__ src_in,
    const float* __restrict__ b1, const float* __restrict__ b2, int iter)
{
    if (iter >= g_sel.n_evolve) return;
    const float* __restrict__ src = iter ? g_buf[iter & 1] : src_in;
    float* __restrict__ dst = g_buf[(iter + 1) & 1];

    extern __shared__ char sm[];
    const uint32_t sb = smem_u32(sm);
    const int tid = threadIdx.x, w = tid >> 5, lane = tid & 31;
    const int m0 = blockIdx.x*128, bidx = m0 >> 12, t0 = m0 & 4095;

    // ---- load 130-row halo'd cells tile -> bf16 hi/lo planes ----
    for (int idx = tid; idx < 130*32; idx += 512) {
        int row = idx >> 5, q = idx & 31;
        int tt = (t0 - 1 + row) & 4095;
        float4 v = __ldg((const float4*)&src[((size_t)(bidx << 12) + tt)*128 + q*4]);
        __nv_bfloat16 h0 = __float2bfloat16_rn(v.x), h1 = __float2bfloat16_rn(v.y);
        __nv_bfloat16 h2 = __float2bfloat16_rn(v.z), h3 = __float2bfloat16_rn(v.w);
        uint32_t lo01 = pack_bf2(v.x - __bfloat162float(h0), v.y - __bfloat162float(h1));
        uint32_t lo23 = pack_bf2(v.z - __bfloat162float(h2), v.w - __bfloat162float(h3));
        __nv_bfloat162 hp0; hp0.x = h0; hp0.y = h1;
        __nv_bfloat162 hp1; hp1.x = h2; hp1.y = h3;
        *(uint2*)(sm + OFF_CH + row*272 + q*8) = make_uint2(*(uint32_t*)&hp0, *(uint32_t*)&hp1);
        *(uint2*)(sm + OFF_CL + row*272 + q*8) = make_uint2(lo01, lo23);
    }

    const int mw  = w & 7;            // 16-row M slice (0..7)
    const int nw  = w >> 3;           // N half
    const int nb1 = nw*32;            // GEMM1 cols (of 64)
    const int nb2 = nw*64;            // GEMM2 cols (of 128)
    const int lrow  = lane & 15;
    const int lsel8 = (lane >> 4) << 3;
    const int nrB   = (lane & 7) + ((lane >> 4) << 3);
    const int selB16 = ((lane >> 3) & 1) * 16;

    float acc2[8][4];
    float outa[8][4];
    #pragma unroll
    for (int j = 0; j < 8; j++)
        #pragma unroll
        for (int q = 0; q < 4; q++) outa[j][q] = 0.f;

    #pragma unroll 1
    for (int r = 0; r < 8; r++) {
        #pragma unroll
        for (int j = 0; j < 8; j++)
            #pragma unroll
            for (int q = 0; q < 4; q++) acc2[j][q] = 0.f;

        #pragma unroll 1
        for (int nh = 0; nh < 2; nh++) {
            #pragma unroll 1
            for (int kc = 0; kc < 2; kc++) {
                // ============ GEMM1: C1[128x64] over K=384, k64 chunks ============
                float C1[4][4];
                #pragma unroll
                for (int j = 0; j < 4; j++)
                    #pragma unroll
                    for (int q = 0; q < 4; q++) C1[j][q] = 0.f;

                __syncthreads();                  // W region free (prev GEMM2 done)
                stage_w1_async(sb, tid, r, nh, kc, 0, 0);
                CP_COMMIT();
                #pragma unroll 1
                for (int c = 0; c < 6; c++) {
                    CP_WAIT0();                   // chunk c landed
                    __syncthreads();              // visible to all; prev buf free
                    if (c + 1 < 6) {
                        stage_w1_async(sb, tid, r, nh, kc, c + 1, (c + 1) & 1);
                        CP_COMMIT();              // retires during chunk-c MMAs
                    }
                    const int p = c >> 1, kcol = (c & 1)*64;
                    const int dp = (p == 0) ? 0 : ((p == 1) ? -1 : 1);
                    const uint32_t aH = sb + OFF_CH
                        + (uint32_t)(mw*16 + 1 + dp + lrow)*272 + (uint32_t)(kcol + lsel8)*2;
                    const uint32_t aL = aH + (OFF_CL - OFF_CH);
                    const uint32_t wb = sb + OFF_W + (uint32_t)(c & 1)*W1BUF
                        + (uint32_t)(nb1 + nrB)*144 + (uint32_t)selB16;
                    #pragma unroll
                    for (int kk = 0; kk < 4; kk++) {
                        uint32_t ah[4], al[4];
                        ldsm4(ah, aH + kk*32);
                        ldsm4(al, aL + kk*32);
                        #pragma unroll
                        for (int g = 0; g < 2; g++) {
                            uint32_t bh[4], bl[4];
                            ldsm4(bh, wb + (uint32_t)g*(16*144) + kk*32);
                            ldsm4(bl, wb + W1LO + (uint32_t)g*(16*144) + kk*32);
                            mma16816(C1[g*2+0], ah, bh[0], bh[1]);
                            mma16816(C1[g*2+1], ah, bh[2], bh[3]);
                            mma16816(C1[g*2+0], al, bh[0], bh[1]);
                            mma16816(C1[g*2+1], al, bh[2], bh[3]);
                            mma16816(C1[g*2+0], ah, bl[0], bl[1]);
                            mma16816(C1[g*2+1], ah, bl[2], bl[3]);
                        }
                    }
                }
                __syncthreads();                  // all warps done with W region
                // ---- W2 cp.async first (overlaps GELU math), then GELU -> H ----
                stage_w2_async(sb, tid, r, nh, kc);
                CP_COMMIT();
                #pragma unroll
                for (int nt = 0; nt < 4; nt++) {
                    int row = mw*16 + (lane >> 2);
                    int colh = nb1 + nt*8 + (lane & 3)*2;
                    float2 bb = *(const float2*)&b1[r*256 + nh*128 + kc*64 + colh];
                    float g0 = gelu_exact(C1[nt][0] + bb.x);
                    float g1 = gelu_exact(C1[nt][1] + bb.y);
                    float g2 = gelu_exact(C1[nt][2] + bb.x);
                    float g3 = gelu_exact(C1[nt][3] + bb.y);
                    __nv_bfloat16 q0 = __float2bfloat16_rn(g0), q1 = __float2bfloat16_rn(g1);
                    __nv_bfloat16 q2 = __float2bfloat16_rn(g2), q3 = __float2bfloat16_rn(g3);
                    __nv_bfloat162 t01; t01.x = q0; t01.y = q1;
                    __nv_bfloat162 t23; t23.x = q2; t23.y = q3;
                    *(uint32_t*)(sm + OFF_HH + row*144 + colh*2)     = *(uint32_t*)&t01;
                    *(uint32_t*)(sm + OFF_HH + (row+8)*144 + colh*2) = *(uint32_t*)&t23;
                    *(uint32_t*)(sm + OFF_HL + row*144 + colh*2)     =
                        pack_bf2(g0 - __bfloat162float(q0), g1 - __bfloat162float(q1));
                    *(uint32_t*)(sm + OFF_HL + (row+8)*144 + colh*2) =
                        pack_bf2(g2 - __bfloat162float(q2), g3 - __bfloat162float(q3));
                }
                CP_WAIT0();
                __syncthreads();
                // ============ GEMM2: acc2 += H[128x64] @ W2[64x128] ============
                const uint32_t hH = sb + OFF_HH + (uint32_t)(mw*16 + lrow)*144 + (uint32_t)lsel8*2;
                const uint32_t hL = hH + (OFF_HL - OFF_HH);
                const uint32_t wb2 = sb + OFF_W + (uint32_t)(nb2 + nrB)*144 + (uint32_t)selB16;
                #pragma unroll
                for (int kk = 0; kk < 4; kk++) {
                    uint32_t ah[4], al[4];
                    ldsm4(ah, hH + kk*32);
                    ldsm4(al, hL + kk*32);
                    #pragma unroll
                    for (int g = 0; g < 4; g++) {
                        uint32_t bh[4], bl[4];
                        ldsm4(bh, wb2 + (uint32_t)g*(16*144) + kk*32);
                        ldsm4(bl, wb2 + W2LO + (uint32_t)g*(16*144) + kk*32);
                        mma16816(acc2[g*2+0], ah, bh[0], bh[1]);
                        mma16816(acc2[g*2+1], ah, bh[2], bh[3]);
                        mma16816(acc2[g*2+0], al, bh[0], bh[1]);
                        mma16816(acc2[g*2+1], al, bh[2], bh[3]);
                        mma16816(acc2[g*2+0], ah, bl[0], bl[1]);
                        mma16816(acc2[g*2+1], ah, bl[2], bl[3]);
                    }
                }
            }
        }
        // ---- rule epilogue: outa += rw * tanh(acc2 + b2) ----
        const float rw = g_sel.rulew[r];
        #pragma unroll
        for (int nt = 0; nt < 8; nt++) {
            int col = nb2 + nt*8 + (lane & 3)*2;
            float2 bb = *(const float2*)&b2[r*128 + col];
            outa[nt][0] = fmaf(rw, tanhf(acc2[nt][0] + bb.x), outa[nt][0]);
            outa[nt][1] = fmaf(rw, tanhf(acc2[nt][1] + bb.y), outa[nt][1]);
            outa[nt][2] = fmaf(rw, tanhf(acc2[nt][2] + bb.x), outa[nt][2]);
            outa[nt][3] = fmaf(rw, tanhf(acc2[nt][3] + bb.y), outa[nt][3]);
        }
    }

    // ---- final blend + store ----
    const float alpha = g_sel.alpha, beta = 1.0f - alpha;
    #pragma unroll
    for (int nt = 0; nt < 8; nt++) {
        int row = m0 + mw*16 + (lane >> 2);
        int col = nb2 + nt*8 + (lane & 3)*2;
        float2 s0 = *(const float2*)&src[(size_t)row*128 + col];
        float2 s1 = *(const float2*)&src[(size_t)(row+8)*128 + col];
        float2 o0, o1;
        o0.x = alpha*s0.x + beta*outa[nt][0];
        o0.y = alpha*s0.y + beta*outa[nt][1];
        o1.x = alpha*s1.x + beta*outa[nt][2];
        o1.y = alpha*s1.y + beta*outa[nt][3];
        *(float2*)&dst[(size_t)row*128 + col]     = o0;
        *(float2*)&dst[(size_t)(row+8)*128 + col] = o1;
    }
}

// ---------------------------------------------------------------------------
// Final LayerNorm
// ---------------------------------------------------------------------------
__global__ void ln_kernel(const float* __restrict__ g, const float* __restrict__ bt,
                          float* __restrict__ out)
{
    const int warp = threadIdx.x >> 5, lane = threadIdx.x & 31;
    const int row  = blockIdx.x * 8 + warp;
    const float* __restrict__ src = g_buf[g_sel.n_evolve & 1];
    float4 v = *(const float4*)&src[(size_t)row*128 + lane*4];
    float s  = v.x + v.y + v.z + v.w;
    float sq = v.x*v.x + v.y*v.y + v.z*v.z + v.w*v.w;
    #pragma unroll
    for (int o = 16; o; o >>= 1) {
        s  += __shfl_xor_sync(0xffffffffu, s,  o);
        sq += __shfl_xor_sync(0xffffffffu, sq, o);
    }
    float mu  = s * (1.0f/128.0f);
    float var = sq * (1.0f/128.0f) - mu*mu;
    float rs  = rsqrtf(var + 1e-5f);
    float4 gv = *(const float4*)&g[lane*4];
    float4 bv = *(const float4*)&bt[lane*4];
    float4 o4;
    o4.x = (v.x - mu)*rs*gv.x + bv.x;
    o4.y = (v.y - mu)*rs*gv.y + bv.y;
    o4.z = (v.z - mu)*rs*gv.z + bv.z;
    o4.w = (v.w - mu)*rs*gv.w + bv.w;
    *(float4*)&out[(size_t)row*128 + lane*4] = o4;
}

// ---------------------------------------------------------------------------
extern "C" void kernel_launch(void* const* d_in, const int* in_sizes, int n_in,
                              void* d_out, int out_size)
{
    const float* cells = (const float*)d_in[0];
    const float* c_st  = (const float*)d_in[1];
    const float* W1    = (const float*)d_in[2];
    const float* b1    = (const float*)d_in[3];
    const float* W2    = (const float*)d_in[4];
    const float* b2    = (const float*)d_in[5];
    const float* rW1   = (const float*)d_in[6];
    const float* rb1   = (const float*)d_in[7];
    const float* rW2   = (const float*)d_in[8];
    const float* rb2   = (const float*)d_in[9];
    const float* sW1   = (const float*)d_in[10];
    const float* sb1   = (const float*)d_in[11];
    const float* sW2   = (const float*)d_in[12];
    const float* sb2   = (const float*)d_in[13];
    const float* aW1   = (const float*)d_in[14];
    const float* ab1   = (const float*)d_in[15];
    const float* aW2   = (const float*)d_in[16];
    const float* ab2   = (const float*)d_in[17];
    const float* lng   = (const float*)d_in[18];
    const float* lnb   = (const float*)d_in[19];
    float* out = (float*)d_out;

    cudaFuncSetAttribute(evolve_mma, cudaFuncAttributeMaxDynamicSharedMemorySize, SMEM_BYTES);

    prep_w1<<<3072, 256>>>(W1);
    prep_w2<<<1024, 256>>>(W2);
    selector_kernel<<<1, 128>>>(c_st, rW1, rb1, rW2, rb2,
                                sW1, sb1, sW2, sb2, aW1, ab1, aW2, ab2);
    for (int i = 0; i < 8; i++)
        evolve_mma<<<256, 512, SMEM_BYTES>>>(cells, b1, b2, i);
    ln_kernel<<<B_*T_/8, 256>>>(lng, lnb, out);
}

// round 17
// speedup vs baseline: 1.9453x; 1.0144x over previous
#include <cuda_runtime.h>
#include <cuda_bf16.h>
#include <stdint.h>
#include <math.h>

#define B_ 8
#define T_ 4096

// smem layout (bytes) — 128-row tile, 512-thread CTA, m32xn32 warp tiles
#define OFF_CH 0          // cells hi: 130 rows x 272B
#define OFF_CL 35360      // cells lo
#define OFF_HH 70720      // H hi: 128 x 272B (128 bf16 cols + pad)
#define OFF_HL 105536     // H lo
#define OFF_W  140352     // W: 2 buffers x (hi 10240 + lo 10240), [128n x 32k] chunks
#define WBUF   20480
#define WLO    10240
#define SMEM_BYTES 181312

struct Sel { float rulew[8]; float alpha; int n_evolve; };
__device__ Sel g_sel;
__device__ float g_buf[2][B_*T_*128];          // ping-pong state
__device__ __nv_bfloat16 g_w1h[8*256*384];     // [r][n=256][k=384] hi
__device__ __nv_bfloat16 g_w1l[8*256*384];     // lo
__device__ __nv_bfloat16 g_w2h[8*128*256];     // [r][n=128][k=256] hi
__device__ __nv_bfloat16 g_w2l[8*128*256];     // lo

__device__ __forceinline__ float gelu_exact(float x){
    return 0.5f*x*(1.0f+erff(x*0.70710678118654752f));
}
__device__ __forceinline__ uint32_t smem_u32(const void* p){
    uint32_t a;
    asm("{ .reg .u64 t; cvta.to.shared.u64 t, %1; cvt.u32.u64 %0, t; }" : "=r"(a) : "l"(p));
    return a;
}
__device__ __forceinline__ void ldsm4(uint32_t* r, uint32_t addr){
    asm volatile("ldmatrix.sync.aligned.m8n8.x4.shared.b16 {%0,%1,%2,%3}, [%4];"
        : "=r"(r[0]),"=r"(r[1]),"=r"(r[2]),"=r"(r[3]) : "r"(addr));
}
__device__ __forceinline__ void mma16816(float* c, const uint32_t* a, uint32_t b0, uint32_t b1){
    asm volatile("mma.sync.aligned.m16n8k16.row.col.f32.bf16.bf16.f32 "
        "{%0,%1,%2,%3}, {%4,%5,%6,%7}, {%8,%9}, {%0,%1,%2,%3};"
        : "+f"(c[0]),"+f"(c[1]),"+f"(c[2]),"+f"(c[3])
        : "r"(a[0]),"r"(a[1]),"r"(a[2]),"r"(a[3]), "r"(b0),"r"(b1));
}
__device__ __forceinline__ uint32_t pack_bf2(float a, float b){
    __nv_bfloat162 t; t.x = __float2bfloat16_rn(a); t.y = __float2bfloat16_rn(b);
    return *(uint32_t*)&t;
}
__device__ __forceinline__ void cp16(uint32_t daddr, const void* gptr){
    asm volatile("cp.async.cg.shared.global [%0], [%1], 16;" :: "r"(daddr), "l"(gptr) : "memory");
}
#define CP_COMMIT() asm volatile("cp.async.commit_group;" ::: "memory")
#define CP_WAIT0()  asm volatile("cp.async.wait_group 0;" ::: "memory")

// ---------------------------------------------------------------------------
// Weight prep: transpose + fp32 -> bf16 hi/lo split
// ---------------------------------------------------------------------------
__global__ void prep_w1(const float* __restrict__ W1){
    int idx = blockIdx.x*256 + threadIdx.x;        // 786432
    int r = idx / 98304, rem = idx - r*98304;
    int k = rem >> 8, n = rem & 255;
    float v = W1[idx];
    __nv_bfloat16 hi = __float2bfloat16_rn(v);
    size_t o = (size_t)(r*256 + n)*384 + k;
    g_w1h[o] = hi;
    g_w1l[o] = __float2bfloat16_rn(v - __bfloat162float(hi));
}
__global__ void prep_w2(const float* __restrict__ W2){
    int idx = blockIdx.x*256 + threadIdx.x;        // 262144
    int r = idx >> 15, rem = idx & 32767;
    int h = rem >> 7, n = rem & 127;
    float v = W2[idx];
    __nv_bfloat16 hi = __float2bfloat16_rn(v);
    size_t o = (size_t)(r*128 + n)*256 + h;
    g_w2h[o] = hi;
    g_w2l[o] = __float2bfloat16_rn(v - __bfloat162float(hi));
}

// ---------------------------------------------------------------------------
// Selector
// ---------------------------------------------------------------------------
__global__ void selector_kernel(const float* __restrict__ c,
    const float* __restrict__ rW1, const float* __restrict__ rb1,
    const float* __restrict__ rW2, const float* __restrict__ rb2,
    const float* __restrict__ sW1, const float* __restrict__ sb1,
    const float* __restrict__ sW2, const float* __restrict__ sb2,
    const float* __restrict__ aW1, const float* __restrict__ ab1,
    const float* __restrict__ aW2, const float* __restrict__ ab2)
{
    __shared__ float cs[128], hidA[64], logA[8], hidB[32], logB[7], hidC[32];
    int t = threadIdx.x;
    cs[t] = c[t];
    __syncthreads();
    if (t < 64) {
        float s = rb1[t];
        for (int k = 0; k < 128; k++) s = fmaf(cs[k], rW1[k*64 + t], s);
        hidA[t] = gelu_exact(s);
    } else if (t < 96) {
        int j = t - 64; float s = sb1[j];
        for (int k = 0; k < 128; k++) s = fmaf(cs[k], sW1[k*32 + j], s);
        hidB[j] = gelu_exact(s);
    } else {
        int j = t - 96; float s = ab1[j];
        for (int k = 0; k < 128; k++) s = fmaf(cs[k], aW1[k*32 + j], s);
        hidC[j] = gelu_exact(s);
    }
    __syncthreads();
    if (t < 8) {
        float s = rb2[t];
        for (int k = 0; k < 64; k++) s = fmaf(hidA[k], rW2[k*8 + t], s);
        logA[t] = s;
    } else if (t < 15) {
        int j = t - 8; float s = sb2[j];
        for (int k = 0; k < 32; k++) s = fmaf(hidB[k], sW2[k*7 + j], s);
        logB[j] = s;
    }
    __syncthreads();
    if (t == 0) {
        float m = -1e30f;
        for (int i = 0; i < 8; i++) m = fmaxf(m, logA[i]);
        float e[8], den = 0.f;
        for (int i = 0; i < 8; i++) { e[i] = expf(logA[i] - m); den += e[i]; }
        for (int i = 0; i < 8; i++) g_sel.rulew[i] = e[i] / den;
    } else if (t == 1) {
        float m = -1e30f;
        for (int i = 0; i < 7; i++) m = fmaxf(m, logB[i]);
        float e[7], den = 0.f;
        for (int i = 0; i < 7; i++) { e[i] = expf(logB[i] - m); den += e[i]; }
        float ns = 0.f;
        for (int i = 0; i < 7; i++) ns += (e[i] / den) * (2.0f + (float)i);
        int n = (int)floorf(ns + 0.5f);
        g_sel.n_evolve = max(2, min(8, n));
    } else if (t == 2) {
        float s = ab2[0];
        for (int k = 0; k < 32; k++) s = fmaf(hidC[k], aW2[k], s);
        g_sel.alpha = 0.1f + 0.8f / (1.0f + expf(-s));
    }
}

// ---------------------------------------------------------------------------
// Async W staging: chunk [128 n-rows x 32 k] hi+lo, 80B row stride.
// 512 threads x (1 cp16 hi + 1 cp16 lo).
// ---------------------------------------------------------------------------
__device__ __forceinline__ void stage_w1_async(uint32_t sb, int tid, int r, int nh,
                                               int c, int buf){
    int row = tid >> 2, q = tid & 3;
    size_t so = (size_t)(r*256 + nh*128 + row)*384 + c*32 + q*8;
    uint32_t d = sb + OFF_W + (uint32_t)buf*WBUF + (uint32_t)row*80 + (uint32_t)q*16;
    cp16(d,       g_w1h + so);
    cp16(d + WLO, g_w1l + so);
}
__device__ __forceinline__ void stage_w2_async(uint32_t sb, int tid, int r, int nh,
                                               int c2, int buf){
    int row = tid >> 2, q = tid & 3;
    size_t so = (size_t)(r*128 + row)*256 + nh*128 + c2*32 + q*8;
    uint32_t d = sb + OFF_W + (uint32_t)buf*WBUF + (uint32_t)row*80 + (uint32_t)q*16;
    cp16(d,       g_w2h + so);
    cp16(d + WLO, g_w2l + so);
}

// ---------------------------------------------------------------------------
// Fused evolve step: 128-row tiles, 512 threads (16 warps = 4M x 4N, m32xn32)
// ---------------------------------------------------------------------------
__global__ void __launch_bounds__(512, 1) evolve_mma(
    const float* __restrict__ src_in,
    const float* __restrict__ b1, const float* __restrict__ b2, int iter)
{
    if (iter >= g_sel.n_evolve) return;
    const float* __restrict__ src = iter ? g_buf[iter & 1] : src_in;
    float* __restrict__ dst = g_buf[(iter + 1) & 1];

    extern __shared__ char sm[];
    const uint32_t sb = smem_u32(sm);
    const int tid = threadIdx.x, w = tid >> 5, lane = tid & 31;
    const int m0 = blockIdx.x*128, bidx = m0 >> 12, t0 = m0 & 4095;

    // ---- load 130-row halo'd cells tile -> bf16 hi/lo planes ----
    for (int idx = tid; idx < 130*32; idx += 512) {
        int row = idx >> 5, q = idx & 31;
        int tt = (t0 - 1 + row) & 4095;
        float4 v = __ldg((const float4*)&src[((size_t)(bidx << 12) + tt)*128 + q*4]);
        __nv_bfloat16 h0 = __float2bfloat16_rn(v.x), h1 = __float2bfloat16_rn(v.y);
        __nv_bfloat16 h2 = __float2bfloat16_rn(v.z), h3 = __float2bfloat16_rn(v.w);
        uint32_t lo01 = pack_bf2(v.x - __bfloat162float(h0), v.y - __bfloat162float(h1));
        uint32_t lo23 = pack_bf2(v.z - __bfloat162float(h2), v.w - __bfloat162float(h3));
        __nv_bfloat162 hp0; hp0.x = h0; hp0.y = h1;
        __nv_bfloat162 hp1; hp1.x = h2; hp1.y = h3;
        *(uint2*)(sm + OFF_CH + row*272 + q*8) = make_uint2(*(uint32_t*)&hp0, *(uint32_t*)&hp1);
        *(uint2*)(sm + OFF_CL + row*272 + q*8) = make_uint2(lo01, lo23);
    }

    const int mw  = w & 3;            // 32-row M slice (0..3)
    const int nwg = w >> 2;           // 32-col N group (0..3)
    const int lrow  = lane & 15;
    const int lsel8 = (lane >> 4) << 3;
    const int nrB   = (lane & 7) + ((lane >> 4) << 3);
    const int selB16 = ((lane >> 3) & 1) * 16;

    float acc2[2][4][4];
    float outa[2][4][4];
    #pragma unroll
    for (int mt = 0; mt < 2; mt++)
        #pragma unroll
        for (int fr = 0; fr < 4; fr++)
            #pragma unroll
            for (int q = 0; q < 4; q++) outa[mt][fr][q] = 0.f;

    #pragma unroll 1
    for (int r = 0; r < 8; r++) {
        #pragma unroll
        for (int mt = 0; mt < 2; mt++)
            #pragma unroll
            for (int fr = 0; fr < 4; fr++)
                #pragma unroll
                for (int q = 0; q < 4; q++) acc2[mt][fr][q] = 0.f;

        #pragma unroll 1
        for (int nh = 0; nh < 2; nh++) {
            // ===== GEMM1: C1[128x128] over K=384, twelve k32 chunks =====
            float C1[2][4][4];
            #pragma unroll
            for (int mt = 0; mt < 2; mt++)
                #pragma unroll
                for (int fr = 0; fr < 4; fr++)
                    #pragma unroll
                    for (int q = 0; q < 4; q++) C1[mt][fr][q] = 0.f;

            stage_w1_async(sb, tid, r, nh, 0, 0);
            CP_COMMIT();
            #pragma unroll 1
            for (int c = 0; c < 12; c++) {
                CP_WAIT0();
                __syncthreads();
                if (c + 1 < 12) {
                    stage_w1_async(sb, tid, r, nh, c + 1, (c + 1) & 1);
                    CP_COMMIT();
                }
                const int p = c >> 2;
                const int dp = (p == 0) ? 0 : ((p == 1) ? -1 : 1);
                const int kcol = (c & 3)*32;
                const uint32_t aB = sb + OFF_CH
                    + (uint32_t)(mw*32 + 1 + dp + lrow)*272 + (uint32_t)(kcol + lsel8)*2;
                const uint32_t wB = sb + OFF_W + (uint32_t)(c & 1)*WBUF
                    + (uint32_t)(nwg*32 + nrB)*80 + (uint32_t)selB16;
                #pragma unroll
                for (int kk = 0; kk < 2; kk++) {
                    uint32_t ah[2][4], al[2][4];
                    #pragma unroll
                    for (int mt = 0; mt < 2; mt++) {
                        ldsm4(ah[mt], aB + mt*(16*272) + kk*32);
                        ldsm4(al[mt], aB + (OFF_CL-OFF_CH) + mt*(16*272) + kk*32);
                    }
                    #pragma unroll
                    for (int g = 0; g < 2; g++) {
                        uint32_t bh[4], bl[4];
                        ldsm4(bh, wB + (uint32_t)g*(16*80) + kk*32);
                        ldsm4(bl, wB + WLO + (uint32_t)g*(16*80) + kk*32);
                        #pragma unroll
                        for (int mt = 0; mt < 2; mt++) {
                            mma16816(C1[mt][2*g],   ah[mt], bh[0], bh[1]);
                            mma16816(C1[mt][2*g+1], ah[mt], bh[2], bh[3]);
                            mma16816(C1[mt][2*g],   al[mt], bh[0], bh[1]);
                            mma16816(C1[mt][2*g+1], al[mt], bh[2], bh[3]);
                            mma16816(C1[mt][2*g],   ah[mt], bl[0], bl[1]);
                            mma16816(C1[mt][2*g+1], ah[mt], bl[2], bl[3]);
                        }
                    }
                }
            }
            __syncthreads();                  // all reads of W1 bufs done
            // ---- W2 chunk0 cp.async first (overlaps GELU), then GELU -> H ----
            stage_w2_async(sb, tid, r, nh, 0, 0);
            CP_COMMIT();
            #pragma unroll
            for (int mt = 0; mt < 2; mt++)
                #pragma unroll
                for (int fr = 0; fr < 4; fr++) {
                    int row = mw*32 + mt*16 + (lane >> 2);
                    int col = nwg*32 + fr*8 + (lane & 3)*2;
                    float2 bb = __ldg((const float2*)&b1[r*256 + nh*128 + col]);
                    float g0 = gelu_exact(C1[mt][fr][0] + bb.x);
                    float g1 = gelu_exact(C1[mt][fr][1] + bb.y);
                    float g2 = gelu_exact(C1[mt][fr][2] + bb.x);
                    float g3 = gelu_exact(C1[mt][fr][3] + bb.y);
                    __nv_bfloat16 q0 = __float2bfloat16_rn(g0), q1 = __float2bfloat16_rn(g1);
                    __nv_bfloat16 q2 = __float2bfloat16_rn(g2), q3 = __float2bfloat16_rn(g3);
                    __nv_bfloat162 t01; t01.x = q0; t01.y = q1;
                    __nv_bfloat162 t23; t23.x = q2; t23.y = q3;
                    *(uint32_t*)(sm + OFF_HH + row*272 + col*2)     = *(uint32_t*)&t01;
                    *(uint32_t*)(sm + OFF_HH + (row+8)*272 + col*2) = *(uint32_t*)&t23;
                    *(uint32_t*)(sm + OFF_HL + row*272 + col*2)     =
                        pack_bf2(g0 - __bfloat162float(q0), g1 - __bfloat162float(q1));
                    *(uint32_t*)(sm + OFF_HL + (row+8)*272 + col*2) =
                        pack_bf2(g2 - __bfloat162float(q2), g3 - __bfloat162float(q3));
                }
            // ===== GEMM2: acc2 += H[128x128] @ W2[128n x 128k], four k32 chunks =====
            #pragma unroll 1
            for (int c2 = 0; c2 < 4; c2++) {
                CP_WAIT0();
                __syncthreads();              // chunk landed + H visible (c2==0)
                if (c2 + 1 < 4) {
                    stage_w2_async(sb, tid, r, nh, c2 + 1, (c2 + 1) & 1);
                    CP_COMMIT();
                }
                const uint32_t hB = sb + OFF_HH
                    + (uint32_t)(mw*32 + lrow)*272 + (uint32_t)(c2*32 + lsel8)*2;
                const uint32_t wB2 = sb + OFF_W + (uint32_t)(c2 & 1)*WBUF
                    + (uint32_t)(nwg*32 + nrB)*80 + (uint32_t)selB16;
                #pragma unroll
                for (int kk = 0; kk < 2; kk++) {
                    uint32_t ah[2][4], al[2][4];
                    #pragma unroll
                    for (int mt = 0; mt < 2; mt++) {
                        ldsm4(ah[mt], hB + mt*(16*272) + kk*32);
                        ldsm4(al[mt], hB + (OFF_HL-OFF_HH) + mt*(16*272) + kk*32);
                    }
                    #pragma unroll
                    for (int g = 0; g < 2; g++) {
                        uint32_t bh[4], bl[4];
                        ldsm4(bh, wB2 + (uint32_t)g*(16*80) + kk*32);
                        ldsm4(bl, wB2 + WLO + (uint32_t)g*(16*80) + kk*32);
                        #pragma unroll
                        for (int mt = 0; mt < 2; mt++) {
                            mma16816(acc2[mt][2*g],   ah[mt], bh[0], bh[1]);
                            mma16816(acc2[mt][2*g+1], ah[mt], bh[2], bh[3]);
                            mma16816(acc2[mt][2*g],   al[mt], bh[0], bh[1]);
                            mma16816(acc2[mt][2*g+1], al[mt], bh[2], bh[3]);
                            mma16816(acc2[mt][2*g],   ah[mt], bl[0], bl[1]);
                            mma16816(acc2[mt][2*g+1], ah[mt], bl[2], bl[3]);
                        }
                    }
                }
            }
        }
        // ---- rule epilogue: outa += rw * tanh(acc2 + b2) ----
        const float rw = g_sel.rulew[r];
        #pragma unroll
        for (int mt = 0; mt < 2; mt++)
            #pragma unroll
            for (int fr = 0; fr < 4; fr++) {
                int col = nwg*32 + fr*8 + (lane & 3)*2;
                float2 bb = __ldg((const float2*)&b2[r*128 + col]);
                outa[mt][fr][0] = fmaf(rw, tanhf(acc2[mt][fr][0] + bb.x), outa[mt][fr][0]);
                outa[mt][fr][1] = fmaf(rw, tanhf(acc2[mt][fr][1] + bb.y), outa[mt][fr][1]);
                outa[mt][fr][2] = fmaf(rw, tanhf(acc2[mt][fr][2] + bb.x), outa[mt][fr][2]);
                outa[mt][fr][3] = fmaf(rw, tanhf(acc2[mt][fr][3] + bb.y), outa[mt][fr][3]);
            }
    }

    // ---- final blend + store ----
    const float alpha = g_sel.alpha, beta = 1.0f - alpha;
    #pragma unroll
    for (int mt = 0; mt < 2; mt++)
        #pragma unroll
        for (int fr = 0; fr < 4; fr++) {
            int row = m0 + mw*32 + mt*16 + (lane >> 2);
            int col = nwg*32 + fr*8 + (lane & 3)*2;
            float2 s0 = *(const float2*)&src[(size_t)row*128 + col];
            float2 s1 = *(const float2*)&src[(size_t)(row+8)*128 + col];
            float2 o0, o1;
            o0.x = alpha*s0.x + beta*outa[mt][fr][0];
            o0.y = alpha*s0.y + beta*outa[mt][fr][1];
            o1.x = alpha*s1.x + beta*outa[mt][fr][2];
            o1.y = alpha*s1.y + beta*outa[mt][fr][3];
            *(float2*)&dst[(size_t)row*128 + col]     = o0;
            *(float2*)&dst[(size_t)(row+8)*128 + col] = o1;
        }
}

// ---------------------------------------------------------------------------
// Final LayerNorm
// ---------------------------------------------------------------------------
__global__ void ln_kernel(const float* __restrict__ g, const float* __restrict__ bt,
                          float* __restrict__ out)
{
    const int warp = threadIdx.x >> 5, lane = threadIdx.x & 31;
    const int row  = blockIdx.x * 8 + warp;
    const float* __restrict__ src = g_buf[g_sel.n_evolve & 1];
    float4 v = *(const float4*)&src[(size_t)row*128 + lane*4];
    float s  = v.x + v.y + v.z + v.w;
    float sq = v.x*v.x + v.y*v.y + v.z*v.z + v.w*v.w;
    #pragma unroll
    for (int o = 16; o; o >>= 1) {
        s  += __shfl_xor_sync(0xffffffffu, s,  o);
        sq += __shfl_xor_sync(0xffffffffu, sq, o);
    }
    float mu  = s * (1.0f/128.0f);
    float var = sq * (1.0f/128.0f) - mu*mu;
    float rs  = rsqrtf(var + 1e-5f);
    float4 gv = *(const float4*)&g[lane*4];
    float4 bv = *(const float4*)&bt[lane*4];
    float4 o4;
    o4.x = (v.x - mu)*rs*gv.x + bv.x;
    o4.y = (v.y - mu)*rs*gv.y + bv.y;
    o4.z = (v.z - mu)*rs*gv.z + bv.z;
    o4.w = (v.w - mu)*rs*gv.w + bv.w;
    *(float4*)&out[(size_t)row*128 + lane*4] = o4;
}

// ---------------------------------------------------------------------------
extern "C" void kernel_launch(void* const* d_in, const int* in_sizes, int n_in,
                              void* d_out, int out_size)
{
    const float* cells = (const float*)d_in[0];
    const float* c_st  = (const float*)d_in[1];
    const float* W1    = (const float*)d_in[2];
    const float* b1    = (const float*)d_in[3];
    const float* W2    = (const float*)d_in[4];
    const float* b2    = (const float*)d_in[5];
    const float* rW1   = (const float*)d_in[6];
    const float* rb1   = (const float*)d_in[7];
    const float* rW2   = (const float*)d_in[8];
    const float* rb2   = (const float*)d_in[9];
    const float* sW1   = (const float*)d_in[10];
    const float* sb1   = (const float*)d_in[11];
    const float* sW2   = (const float*)d_in[12];
    const float* sb2   = (const float*)d_in[13];
    const float* aW1   = (const float*)d_in[14];
    const float* ab1   = (const float*)d_in[15];
    const float* aW2   = (const float*)d_in[16];
    const float* ab2   = (const float*)d_in[17];
    const float* lng   = (const float*)d_in[18];
    const float* lnb   = (const float*)d_in[19];
    float* out = (float*)d_out;

    cudaFuncSetAttribute(evolve_mma, cudaFuncAttributeMaxDynamicSharedMemorySize, SMEM_BYTES);

    prep_w1<<<3072, 256>>>(W1);
    prep_w2<<<1024, 256>>>(W2);
    selector_kernel<<<1, 128>>>(c_st, rW1, rb1, rW2, rb2,
                                sW1, sb1, sW2, sb2, aW1, ab1, aW2, ab2);
    for (int i = 0; i < 8; i++)
        evolve_mma<<<256, 512, SMEM_BYTES>>>(cells, b1, b2, i);
    ln_kernel<<<B_*T_/8, 256>>>(lng, lnb, out);
}